// round 12
// baseline (speedup 1.0000x reference)
#include <cuda_runtime.h>
#include <cuda_bf16.h>

// Problem shape (fixed by the dataset)
#define B_DIM 16
#define S_DIM 2048
#define D_DIM 256
#define ROWS  (B_DIM * S_DIM)          // 32768
#define QUADS (ROWS / 4)               // 8192
#define P_ASEM 0.6f
#define Q_ASEM 0.4f
#define MASK_FILL 1e-9f

// Scratch (no cudaMalloc allowed)
__device__ float    g_si[ROWS];    // si + bias folded in
__device__ float    g_sj[ROWS];
__device__ unsigned g_rows[ROWS];  // compacted unmasked row indices
__device__ unsigned g_count;       // number of unmasked rows

// ---------------------------------------------------------------------------
// Kernel 0: reset compaction counter (determinism across graph replays).
// ---------------------------------------------------------------------------
__global__ void reset_kernel() { g_count = 0; }

// ---------------------------------------------------------------------------
// Kernel 1 (proj_fill): quad per block (8192 blocks).
//   - warps 0..3: dual dot products for their row (if unmasked)
//   - all threads: MASK_FILL writes for masked rows (134 MB, no proj dep)
//   - thread 0: append unmasked row indices to the compaction list
// ---------------------------------------------------------------------------
__global__ __launch_bounds__(256) void proj_fill_kernel(const float* __restrict__ x,
                                                        const int*   __restrict__ mask,
                                                        const float* __restrict__ W,
                                                        const float* __restrict__ bias,
                                                        float4*      __restrict__ out4) {
    const unsigned tid  = threadIdx.x;
    const int      lane = tid & 31;
    const int      wid  = tid >> 5;
    const unsigned row0 = blockIdx.x << 2;
    const unsigned base = row0 << 9;

    int mi[4];
#pragma unroll
    for (int r = 0; r < 4; ++r) mi[r] = __ldg(&mask[row0 + r]);

    // ---- compaction append (one aggregated atomic per quad) ----
    if (tid == 0) {
        const int nm = mi[0] + mi[1] + mi[2] + mi[3];   // mask values are 0/1
        if (nm) {
            unsigned b = atomicAdd(&g_count, (unsigned)nm);
#pragma unroll
            for (int r = 0; r < 4; ++r)
                if (mi[r]) g_rows[b++] = row0 + r;
        }
    }

    // ---- projections for unmasked rows (warps 0..3, one row each) ----
    if (wid < 4 && mi[wid]) {
        const int row = row0 + wid;
        const float4* x4  = reinterpret_cast<const float4*>(x) + (long)row * (D_DIM / 4);
        const float4* Wi4 = reinterpret_cast<const float4*>(W);            // W[0:256]
        const float4* Wj4 = reinterpret_cast<const float4*>(W + D_DIM);    // W[256:512]

        float4 xv0 = x4[lane];
        float4 xv1 = x4[lane + 32];
        float4 wi0 = __ldg(&Wi4[lane]);
        float4 wi1 = __ldg(&Wi4[lane + 32]);
        float4 wj0 = __ldg(&Wj4[lane]);
        float4 wj1 = __ldg(&Wj4[lane + 32]);

        float si = 0.f, sj = 0.f;
        si = fmaf(xv0.x, wi0.x, si); si = fmaf(xv0.y, wi0.y, si);
        si = fmaf(xv0.z, wi0.z, si); si = fmaf(xv0.w, wi0.w, si);
        si = fmaf(xv1.x, wi1.x, si); si = fmaf(xv1.y, wi1.y, si);
        si = fmaf(xv1.z, wi1.z, si); si = fmaf(xv1.w, wi1.w, si);
        sj = fmaf(xv0.x, wj0.x, sj); sj = fmaf(xv0.y, wj0.y, sj);
        sj = fmaf(xv0.z, wj0.z, sj); sj = fmaf(xv0.w, wj0.w, sj);
        sj = fmaf(xv1.x, wj1.x, sj); sj = fmaf(xv1.y, wj1.y, sj);
        sj = fmaf(xv1.z, wj1.z, sj); sj = fmaf(xv1.w, wj1.w, sj);

#pragma unroll
        for (int off = 16; off > 0; off >>= 1) {
            si += __shfl_down_sync(0xFFFFFFFFu, si, off);
            sj += __shfl_down_sync(0xFFFFFFFFu, sj, off);
        }
        if (lane == 0) {
            g_si[row] = si + __ldg(bias);
            g_sj[row] = sj;
        }
    }

    // ---- fill writes for masked rows (all 256 threads) ----
    const float4 fill = make_float4(MASK_FILL, MASK_FILL, MASK_FILL, MASK_FILL);
#pragma unroll
    for (int r = 0; r < 4; ++r) {
        if (!mi[r]) {
            const unsigned o = base + (r << 9) + tid;
            __stcs(&out4[o], fill);
            __stcs(&out4[o + 256], fill);
        }
    }
}

// ---------------------------------------------------------------------------
// Kernel 2 (blend): DENSE — each block handles 2 compacted unmasked rows
// (full 2048-float rows; 4 float4 loads + 4 stores per thread, MLP=4).
// Fixed worst-case grid; blocks beyond the live count exit immediately.
// ---------------------------------------------------------------------------
__device__ __forceinline__ float sig_blend(float si, float sjv, int m, float a) {
    float z = si + sjv;
    float s = __fdividef(1.f, 1.f + __expf(-z));
    return m ? fmaf(P_ASEM, s, Q_ASEM * a) : MASK_FILL;
}

__global__ __launch_bounds__(256) void blend_kernel(const float4* __restrict__ adj4,
                                                    const int*    __restrict__ mask,
                                                    float4*       __restrict__ out4) {
    const unsigned tid = threadIdx.x;
    const unsigned cnt = g_count;
    const unsigned i0  = blockIdx.x << 1;
    if (i0 >= cnt) return;

    const unsigned row0  = g_rows[i0];
    const bool     have1 = (i0 + 1 < cnt);
    const unsigned row1  = have1 ? g_rows[i0 + 1] : row0;

    const unsigned o0 = (row0 << 9) + tid;
    const unsigned o1 = (row1 << 9) + tid;

    // all adj loads up front (4 independent LDG.128 per thread)
    float4 a0A = __ldcs(&adj4[o0]);
    float4 a0B = __ldcs(&adj4[o0 + 256]);
    float4 a1A, a1B;
    if (have1) {
        a1A = __ldcs(&adj4[o1]);
        a1B = __ldcs(&adj4[o1 + 256]);
    }

    // column vectors per row's batch
    const float4* sj4 = reinterpret_cast<const float4*>(g_sj);
    const int4*   mj4 = reinterpret_cast<const int4*>(mask);
    const unsigned c0 = ((row0 >> 11) << 9) + tid;
    const unsigned c1 = ((row1 >> 11) << 9) + tid;

    const float4 sj0A = __ldg(&sj4[c0]);
    const float4 sj0B = __ldg(&sj4[c0 + 256]);
    const int4   m0A  = __ldg(&mj4[c0]);
    const int4   m0B  = __ldg(&mj4[c0 + 256]);

    const float si0 = g_si[row0];

    float4 out;
    out.x = sig_blend(si0, sj0A.x, m0A.x, a0A.x);
    out.y = sig_blend(si0, sj0A.y, m0A.y, a0A.y);
    out.z = sig_blend(si0, sj0A.z, m0A.z, a0A.z);
    out.w = sig_blend(si0, sj0A.w, m0A.w, a0A.w);
    __stcs(&out4[o0], out);

    out.x = sig_blend(si0, sj0B.x, m0B.x, a0B.x);
    out.y = sig_blend(si0, sj0B.y, m0B.y, a0B.y);
    out.z = sig_blend(si0, sj0B.z, m0B.z, a0B.z);
    out.w = sig_blend(si0, sj0B.w, m0B.w, a0B.w);
    __stcs(&out4[o0 + 256], out);

    if (have1) {
        const float4 sj1A = __ldg(&sj4[c1]);
        const float4 sj1B = __ldg(&sj4[c1 + 256]);
        const int4   m1A  = __ldg(&mj4[c1]);
        const int4   m1B  = __ldg(&mj4[c1 + 256]);
        const float  si1  = g_si[row1];

        out.x = sig_blend(si1, sj1A.x, m1A.x, a1A.x);
        out.y = sig_blend(si1, sj1A.y, m1A.y, a1A.y);
        out.z = sig_blend(si1, sj1A.z, m1A.z, a1A.z);
        out.w = sig_blend(si1, sj1A.w, m1A.w, a1A.w);
        __stcs(&out4[o1], out);

        out.x = sig_blend(si1, sj1B.x, m1B.x, a1B.x);
        out.y = sig_blend(si1, sj1B.y, m1B.y, a1B.y);
        out.z = sig_blend(si1, sj1B.z, m1B.z, a1B.z);
        out.w = sig_blend(si1, sj1B.w, m1B.w, a1B.w);
        __stcs(&out4[o1 + 256], out);
    }
}

// ---------------------------------------------------------------------------
// Launch
// Inputs (metadata order): 0:x [16,2048,256] f32, 1:adj [16,2048,2048] f32,
//                          2:mask [16,2048] i32, 3:W [1,512] f32, 4:b [1] f32
// Output: [16,2048,2048] f32
// ---------------------------------------------------------------------------
extern "C" void kernel_launch(void* const* d_in, const int* in_sizes, int n_in,
                              void* d_out, int out_size) {
    const float* x    = (const float*)d_in[0];
    const float* adj  = (const float*)d_in[1];
    const int*   mask = (const int*)d_in[2];
    const float* W    = (const float*)d_in[3];
    const float* bias = (const float*)d_in[4];
    float4* out = (float4*)d_out;

    reset_kernel<<<1, 1>>>();

    // Kernel 1: projections + masked-row fill + compaction (quad per block)
    proj_fill_kernel<<<QUADS, 256>>>(x, mask, W, bias, out);

    // Kernel 2: dense blend over compacted rows, 2 rows/block worst-case grid
    blend_kernel<<<ROWS / 2, 256>>>(reinterpret_cast<const float4*>(adj),
                                    mask, out);
}